// round 7
// baseline (speedup 1.0000x reference)
#include <cuda_runtime.h>
#include <cuda_fp16.h>
#include <cstdint>

#define BATCH 64
#define NCAP  16
#define DCAP  64
#define NIN   512
#define DIN   1024

// ---------------- scratch (allocation-free: __device__ globals) ----------------
__device__ __half g_xh[(size_t)BATCH * NIN * DIN];       // 64 MB, x f16 [b][j][k]
__device__ float  g_xsump[8][BATCH][DIN];                // 2 MB, partial x sums over j
__device__ float  g_t[(size_t)BATCH * NCAP * DIN];       // 4 MB, t[b][i][k] = W_i @ out_i
__device__ float  g_ypart[8][BATCH][NCAP][DIN];          // 32 MB, y partials

// ---------------- helpers ----------------
__device__ __forceinline__ uint32_t smem_u32(const void* p) {
    uint32_t a;
    asm("{ .reg .u64 t; cvta.to.shared.u64 t, %1; cvt.u32.u64 %0, t; }" : "=r"(a) : "l"(p));
    return a;
}
__device__ __forceinline__ void cp16(uint32_t dst, const void* src) {
    asm volatile("cp.async.cg.shared.global [%0], [%1], 16;\n" :: "r"(dst), "l"(src));
}
__device__ __forceinline__ void cp_commit() { asm volatile("cp.async.commit_group;\n" ::: "memory"); }

// ---------------- pass0: xsum partials + x -> f16 ----------------
__global__ __launch_bounds__(256) void pass0(const float* __restrict__ X) {
    const int c = blockIdx.x, b = blockIdx.y, tid = threadIdx.x;
    const size_t rowbase = ((size_t)b * NIN + c * 64) * DIN;
    const float4* xp = (const float4*)(X + rowbase) + tid;
    uint2* xh = (uint2*)(g_xh + rowbase) + tid;
    float4 a = make_float4(0.f, 0.f, 0.f, 0.f);
#pragma unroll 4
    for (int j = 0; j < 64; j++) {
        const float4 v = xp[j * (DIN / 4)];
        a.x += v.x; a.y += v.y; a.z += v.z; a.w += v.w;
        const __half2 h0 = __floats2half2_rn(v.x, v.y);
        const __half2 h1 = __floats2half2_rn(v.z, v.w);
        uint2 u;
        u.x = *(const unsigned*)&h0;
        u.y = *(const unsigned*)&h1;
        xh[j * (DIN / 4)] = u;
    }
    ((float4*)g_xsump[c][b])[tid] = a;
}

// ---------------- kA: y -> z = y@W_i -> out = squash(z) -> t = W_i@out ----------------
// grid (16 i, 4 bgroup), 512 threads. W f32 from L2.
#define KA_SMEM ((16 * 1024 + 8 * 16 * 64 + 16 * 64) * 4)   // y_s + zred + out_s = 100 KB

__global__ __launch_bounds__(512) void kA(const float* __restrict__ W,
                                          float* __restrict__ d_out, int stage) {
    extern __shared__ float s[];
    float* y_s  = s;                       // [16][1024]
    float* zred = y_s + 16 * 1024;         // [8][16][64]
    float* out_s = zred + 8 * 16 * 64;     // [16][64]

    const int i = blockIdx.x, bg = blockIdx.y, tid = threadIdx.x;
    const int b0 = bg * 16;

    // build y_s: stage0 -> xsum/16 (same for all i); else sum of 8 y partials
    for (int e = tid; e < 16 * 1024; e += 512) {
        const int bl = e >> 10, k = e & 1023;
        float v = 0.f;
        if (stage == 0) {
#pragma unroll
            for (int p = 0; p < 8; p++) v += g_xsump[p][b0 + bl][k];
            v *= (1.f / 16.f);
        } else {
#pragma unroll
            for (int p = 0; p < 8; p++) v += g_ypart[p][b0 + bl][i][k];
        }
        y_s[e] = v;
    }
    __syncthreads();

    // z[bl][d] = sum_k y[bl][k] * W[k][i*64+d], k split 8 ways
    {
        const int ks = tid >> 6, d = tid & 63;
        float acc[16];
#pragma unroll
        for (int q = 0; q < 16; q++) acc[q] = 0.f;
        const float* wp = W + (size_t)(ks * 128) * 1024 + i * 64 + d;
#pragma unroll 4
        for (int k2 = 0; k2 < 64; k2++) {
            const float w0 = wp[(2 * k2) * 1024];
            const float w1 = wp[(2 * k2 + 1) * 1024];
            const int kk = ks * 128 + 2 * k2;
#pragma unroll
            for (int bl = 0; bl < 16; bl++) {
                const float2 yv = *(const float2*)&y_s[bl * 1024 + kk];
                acc[bl] = fmaf(yv.x, w0, fmaf(yv.y, w1, acc[bl]));
            }
        }
#pragma unroll
        for (int bl = 0; bl < 16; bl++) zred[(ks * 16 + bl) * 64 + d] = acc[bl];
    }
    __syncthreads();

    // reduce 8 k-slices + squash; warp w handles bl = w
    {
        const int w = tid >> 5, lane = tid & 31;
        float za = 0.f, zb = 0.f;
#pragma unroll
        for (int p = 0; p < 8; p++) {
            za += zred[(p * 16 + w) * 64 + lane];
            zb += zred[(p * 16 + w) * 64 + lane + 32];
        }
        float sq = za * za + zb * zb;
#pragma unroll
        for (int o = 16; o; o >>= 1) sq += __shfl_xor_sync(0xffffffffu, sq, o);
        const float inv = 1.0f / sqrtf(sq + 1e-7f);
        out_s[w * 64 + lane]      = za * inv;
        out_s[w * 64 + lane + 32] = zb * inv;
        if (stage == 2) {
            float* dp = d_out + ((size_t)(b0 + w) * NCAP + i) * DCAP;
            dp[lane]      = za * inv;
            dp[lane + 32] = zb * inv;
        }
    }
    __syncthreads();
    if (stage == 2) return;

    // t[bl][k] = sum_d W[k][i*64+d] * out[bl][d]
    for (int r = 0; r < 2; r++) {
        const int k = r * 512 + tid;
        const float4* wrow = (const float4*)(W + (size_t)k * 1024 + i * 64);
        float tacc[16];
#pragma unroll
        for (int bl = 0; bl < 16; bl++) tacc[bl] = 0.f;
#pragma unroll
        for (int q = 0; q < 16; q++) {
            const float4 wv = wrow[q];
#pragma unroll
            for (int bl = 0; bl < 16; bl++) {
                const float4 o = *(const float4*)&out_s[bl * 64 + q * 4];
                tacc[bl] = fmaf(wv.x, o.x, fmaf(wv.y, o.y,
                           fmaf(wv.z, o.z, fmaf(wv.w, o.w, tacc[bl]))));
            }
        }
#pragma unroll
        for (int bl = 0; bl < 16; bl++)
            g_t[((size_t)(b0 + bl) * NCAP + i) * DIN + k] = tacc[bl];
    }
}

// ---------------- pass_route: logits (x.t) -> softmax over i -> y partials ----------------
// grid (2 jchunk, 64 b), 512 threads. SMEM 172 KB.
#define JT 256
#define KP 64
#define NPAN (DIN / KP)       // 16
#define XPITH 72              // halves per j row (144 B, 16B-mult)
#define XBUF_H (JT * XPITH)   // 18432 halves per buffer
#define TPIT 20
#define CPIT 20
#define X_BYTES (2 * XBUF_H * 2)                       // 73728
#define T_OFF   X_BYTES
#define C_OFF   (T_OFF + 1024 * TPIT * 4)              // +81920
#define PASS_SMEM (C_OFF + JT * CPIT * 4)              // +20480 = 176128

__global__ __launch_bounds__(512) void pass_route() {
    extern __shared__ char smb[];
    __half* x_s = (__half*)smb;
    float*  t_t = (float*)(smb + T_OFF);   // [k][16] pitch 20
    float*  c_s = (float*)(smb + C_OFF);   // [256][16] pitch 20
    const uint32_t sb = smem_u32(smb);

    const int jc = blockIdx.x, b = blockIdx.y, tid = threadIdx.x;
    const int j0 = jc * JT;

    // stage t transposed: g_t[b][i][k] -> t_t[k][i]
    for (int e = tid; e < NCAP * DIN; e += 512) {
        const int i = e >> 10, k = e & 1023;
        t_t[k * TPIT + i] = g_t[((size_t)b * NCAP + i) * DIN + k];
    }

    auto load_panel = [&](int p) {
        const uint32_t base = sb + (uint32_t)(p & 1) * (XBUF_H * 2);
        const __half* src = g_xh + ((size_t)b * NIN + j0) * DIN + p * KP;
        for (int e = tid; e < JT * 8; e += 512) {
            const int j = e >> 3, c16 = e & 7;
            cp16(base + j * (XPITH * 2) + c16 * 16, src + (size_t)j * DIN + c16 * 8);
        }
        cp_commit();
    };
    load_panel(0);
    load_panel(1);
    __syncthreads();   // t_t visible

    // ---- logits: warp w -> 16 j x 16 i tile ----
    const int lane = tid & 31, w = tid >> 5;
    const int jq = lane >> 2, ig = lane & 3;
    float la[2][4];
#pragma unroll
    for (int r = 0; r < 2; r++)
#pragma unroll
        for (int q = 0; q < 4; q++) la[r][q] = 0.f;

    for (int p = 0; p < NPAN; p++) {
        if (p + 2 < NPAN) asm volatile("cp.async.wait_group 1;\n" ::: "memory");
        else              asm volatile("cp.async.wait_group 0;\n" ::: "memory");
        __syncthreads();
        const __half* xp0 = x_s + (p & 1) * XBUF_H + (w * 16 + jq) * XPITH;
        const __half* xp1 = xp0 + 8 * XPITH;
        const float*  tp  = t_t + (p * KP) * TPIT + ig * 4;
#pragma unroll 16
        for (int k = 0; k < KP; k++) {
            const float4 tv = *(const float4*)(tp + k * TPIT);
            const float x0 = __half2float(xp0[k]);
            const float x1 = __half2float(xp1[k]);
            la[0][0] = fmaf(x0, tv.x, la[0][0]);
            la[0][1] = fmaf(x0, tv.y, la[0][1]);
            la[0][2] = fmaf(x0, tv.z, la[0][2]);
            la[0][3] = fmaf(x0, tv.w, la[0][3]);
            la[1][0] = fmaf(x1, tv.x, la[1][0]);
            la[1][1] = fmaf(x1, tv.y, la[1][1]);
            la[1][2] = fmaf(x1, tv.z, la[1][2]);
            la[1][3] = fmaf(x1, tv.w, la[1][3]);
        }
        __syncthreads();
        if (p + 2 < NPAN) load_panel(p + 2);
    }

    // restart panel stream for y phase (overlaps with softmax)
    load_panel(0);
    load_panel(1);

    // write raw logits
#pragma unroll
    for (int r = 0; r < 2; r++) {
        const int j = w * 16 + jq + r * 8;
        *(float4*)&c_s[j * CPIT + ig * 4] = make_float4(la[r][0], la[r][1], la[r][2], la[r][3]);
    }
    __syncthreads();

    // softmax over the 16 capsules per j
#pragma unroll
    for (int r = 0; r < 8; r++) {
        const int j = r * 32 + (tid >> 4), i = tid & 15;
        const float v = c_s[j * CPIT + i];
        float m = v;
#pragma unroll
        for (int o = 1; o < 16; o <<= 1) m = fmaxf(m, __shfl_xor_sync(0xffffffffu, m, o));
        const float e = expf(v - m);
        float s2 = e;
#pragma unroll
        for (int o = 1; o < 16; o <<= 1) s2 += __shfl_xor_sync(0xffffffffu, s2, o);
        c_s[j * CPIT + i] = e / s2;
    }
    __syncthreads();

    // ---- y: thread (jq2, ig2, kk) accumulates y[4 i][2 k] over its 64 j ----
    const int kk = tid & 31, ig2 = (tid >> 5) & 3, jq2 = tid >> 7;
    for (int p = 0; p < NPAN; p++) {
        if (p + 2 < NPAN) asm volatile("cp.async.wait_group 1;\n" ::: "memory");
        else              asm volatile("cp.async.wait_group 0;\n" ::: "memory");
        __syncthreads();
        const __half* xb = x_s + (p & 1) * XBUF_H + (jq2 * 64) * XPITH;
        const float*  cb = c_s + (jq2 * 64) * CPIT + ig2 * 4;
        float a0[4] = {0.f, 0.f, 0.f, 0.f};
        float a1[4] = {0.f, 0.f, 0.f, 0.f};
#pragma unroll 8
        for (int j = 0; j < 64; j++) {
            const float4 cv = *(const float4*)(cb + j * CPIT);
            const float xv0 = __half2float(xb[j * XPITH + kk]);
            const float xv1 = __half2float(xb[j * XPITH + kk + 32]);
            a0[0] = fmaf(cv.x, xv0, a0[0]);
            a0[1] = fmaf(cv.y, xv0, a0[1]);
            a0[2] = fmaf(cv.z, xv0, a0[2]);
            a0[3] = fmaf(cv.w, xv0, a0[3]);
            a1[0] = fmaf(cv.x, xv1, a1[0]);
            a1[1] = fmaf(cv.y, xv1, a1[1]);
            a1[2] = fmaf(cv.z, xv1, a1[2]);
            a1[3] = fmaf(cv.w, xv1, a1[3]);
        }
        const int kg = p * KP + kk;
#pragma unroll
        for (int q = 0; q < 4; q++) {
            g_ypart[jc * 4 + jq2][b][ig2 * 4 + q][kg]      = a0[q];
            g_ypart[jc * 4 + jq2][b][ig2 * 4 + q][kg + 32] = a1[q];
        }
        __syncthreads();
        if (p + 2 < NPAN) load_panel(p + 2);
    }
}

// ---------------- launch ----------------
extern "C" void kernel_launch(void* const* d_in, const int* in_sizes, int n_in,
                              void* d_out, int out_size) {
    const float* x = (const float*)d_in[0];
    const float* W = (const float*)d_in[1];
    if (in_sizes[0] == DIN * NCAP * DCAP && in_sizes[1] == (int)((size_t)BATCH * NIN * DIN)) {
        const float* t = x; x = W; W = t;
    }
    float* out = (float*)d_out;

    cudaFuncSetAttribute(kA, cudaFuncAttributeMaxDynamicSharedMemorySize, KA_SMEM);
    cudaFuncSetAttribute(pass_route, cudaFuncAttributeMaxDynamicSharedMemorySize, PASS_SMEM);

    pass0<<<dim3(8, BATCH), 256>>>(x);
    kA<<<dim3(NCAP, 4), 512, KA_SMEM>>>(W, out, 0);   // iter0: out0, t0
    pass_route<<<dim3(2, BATCH), 512, PASS_SMEM>>>(); // iter1: logits/softmax/y1
    kA<<<dim3(NCAP, 4), 512, KA_SMEM>>>(W, out, 1);   // iter1: out1, t1
    pass_route<<<dim3(2, BATCH), 512, PASS_SMEM>>>(); // iter2: logits/softmax/y2
    kA<<<dim3(NCAP, 4), 512, KA_SMEM>>>(W, out, 2);   // iter2: final out -> d_out
}

// round 8
// speedup vs baseline: 2.3382x; 2.3382x over previous
#include <cuda_runtime.h>
#include <cuda_fp16.h>
#include <cstdint>

#define BATCH 64
#define NCAP  16
#define DCAP  64
#define NIN   512
#define DIN   1024

// ---------------- scratch (allocation-free: __device__ globals) ----------------
__device__ __half g_xh[(size_t)BATCH * NIN * DIN];       // 64 MB, x f16 [b][j][k]
__device__ __half g_wh16[(size_t)DIN * NCAP * DCAP];     // 2 MB, W f16 [k][n]
__device__ float  g_xsump[8][BATCH][DIN];                // 2 MB, partial x sums over j
__device__ float  g_t[(size_t)BATCH * NCAP * DIN];       // 4 MB, t[b][i][k] = W_i @ out_i
__device__ float  g_ypart[8][BATCH][NCAP][DIN];          // 32 MB, y partials

// ---------------- helpers ----------------
__device__ __forceinline__ uint32_t smem_u32(const void* p) {
    uint32_t a;
    asm("{ .reg .u64 t; cvta.to.shared.u64 t, %1; cvt.u32.u64 %0, t; }" : "=r"(a) : "l"(p));
    return a;
}
__device__ __forceinline__ void cp16(uint32_t dst, const void* src) {
    asm volatile("cp.async.cg.shared.global [%0], [%1], 16;\n" :: "r"(dst), "l"(src));
}
__device__ __forceinline__ void cp_commit() { asm volatile("cp.async.commit_group;\n" ::: "memory"); }

// ---------------- prep: W f32 -> f16 ----------------
__global__ __launch_bounds__(256) void wh16_kernel(const float* __restrict__ W) {
    const size_t n4 = (size_t)DIN * 1024 / 4;
    for (size_t e = (size_t)blockIdx.x * blockDim.x + threadIdx.x; e < n4;
         e += (size_t)gridDim.x * blockDim.x) {
        float4 v = ((const float4*)W)[e];
        __half2* dst = (__half2*)g_wh16 + e * 2;
        dst[0] = __floats2half2_rn(v.x, v.y);
        dst[1] = __floats2half2_rn(v.z, v.w);
    }
}

// ---------------- pass0: xsum partials + x -> f16 ----------------
__global__ __launch_bounds__(256) void pass0(const float* __restrict__ X) {
    const int c = blockIdx.x, b = blockIdx.y, tid = threadIdx.x;
    const size_t rowbase = ((size_t)b * NIN + c * 64) * DIN;
    const float4* xp = (const float4*)(X + rowbase) + tid;
    uint2* xh = (uint2*)(g_xh + rowbase) + tid;
    float4 a = make_float4(0.f, 0.f, 0.f, 0.f);
#pragma unroll 4
    for (int j = 0; j < 64; j++) {
        const float4 v = xp[j * (DIN / 4)];
        a.x += v.x; a.y += v.y; a.z += v.z; a.w += v.w;
        const __half2 h0 = __floats2half2_rn(v.x, v.y);
        const __half2 h1 = __floats2half2_rn(v.z, v.w);
        uint2 u;
        u.x = *(const unsigned*)&h0;
        u.y = *(const unsigned*)&h1;
        xh[j * (DIN / 4)] = u;
    }
    ((float4*)g_xsump[c][b])[tid] = a;
}

// ---------------- kA2: y -> z = y@W_i -> out = squash(z) -> t = W_i@out ----------------
// grid (16 i, 16 bgroup of 4), 512 threads. W_i slice staged f16 in SMEM, reused z+t.
#define KA_W_OFF 0
#define KA_Y_OFF (DIN * DCAP * 2)                    // 131072
#define KA_Z_OFF (KA_Y_OFF + 4 * DIN * 4)            // +16384
#define KA_O_OFF (KA_Z_OFF + 8 * 4 * 64 * 4)         // +8192
#define KA_SMEM  (KA_O_OFF + 4 * 32 * 8)             // +1024 = 156672

__global__ __launch_bounds__(512) void kA2(float* __restrict__ d_out, int stage) {
    extern __shared__ char smb[];
    const uint32_t sb = smem_u32(smb);
    __half*  Wh   = (__half*)smb;                        // [1024][64]
    float*   y_s  = (float*)(smb + KA_Y_OFF);            // [4][1024]
    float*   zred = (float*)(smb + KA_Z_OFF);            // [8][4][64]
    float2*  out2 = (float2*)(smb + KA_O_OFF);           // [4][32] (d pairs)

    const int i = blockIdx.x, bg = blockIdx.y, tid = threadIdx.x;
    const int b0 = bg * 4;
    const int lane = tid & 31;

    // stage W_i slice: 1024 rows x 128B, cp.async
    {
        const __half* src = g_wh16 + i * 64;
#pragma unroll 4
        for (int e = tid; e < 8192; e += 512) {
            const int k = e >> 3, c = e & 7;
            cp16(sb + k * 128 + c * 16, src + (size_t)k * 1024 + c * 8);
        }
        cp_commit();
    }

    // build y_s
    for (int e = tid; e < 4 * DIN; e += 512) {
        const int bl = e >> 10, k = e & 1023;
        float v = 0.f;
        if (stage == 0) {
#pragma unroll
            for (int p = 0; p < 8; p++) v += g_xsump[p][b0 + bl][k];
            v *= (1.f / 16.f);
        } else {
#pragma unroll
            for (int p = 0; p < 8; p++) v += g_ypart[p][b0 + bl][i][k];
        }
        y_s[e] = v;
    }
    asm volatile("cp.async.wait_group 0;\n" ::: "memory");
    __syncthreads();

    // z: thread (ks = tid>>6 of 8 k-slices, d = tid&63)
    {
        const int ks = tid >> 6, d = tid & 63;
        float acc[4] = {0.f, 0.f, 0.f, 0.f};
        const __half* wp = Wh + (size_t)(ks * 128) * 64 + d;
#pragma unroll 8
        for (int k2 = 0; k2 < 128; k2++) {
            const float w = __half2float(wp[k2 * 64]);
            const int k = ks * 128 + k2;
#pragma unroll
            for (int bl = 0; bl < 4; bl++)
                acc[bl] = fmaf(y_s[bl * 1024 + k], w, acc[bl]);
        }
#pragma unroll
        for (int bl = 0; bl < 4; bl++) zred[(ks * 4 + bl) * 64 + d] = acc[bl];
    }
    __syncthreads();

    // reduce 8 slices + squash (4 warps, one per bl; lane = d-pair)
    if (tid < 128) {
        const int bl = tid >> 5;
        float za = 0.f, zb = 0.f;
#pragma unroll
        for (int p = 0; p < 8; p++) {
            za += zred[(p * 4 + bl) * 64 + 2 * lane];
            zb += zred[(p * 4 + bl) * 64 + 2 * lane + 1];
        }
        float sq = za * za + zb * zb;
#pragma unroll
        for (int o = 16; o; o >>= 1) sq += __shfl_xor_sync(0xffffffffu, sq, o);
        const float inv = 1.0f / sqrtf(sq + 1e-7f);
        const float ox = za * inv, oy = zb * inv;
        out2[bl * 32 + lane] = make_float2(ox, oy);
        if (stage == 2) {
            float2* dp = (float2*)(d_out + ((size_t)(b0 + bl) * NCAP + i) * DCAP);
            dp[lane] = make_float2(ox, oy);
        }
    }
    __syncthreads();
    if (stage == 2) return;

    // t: thread covers k = tid and k + 512; rotated W reads (conflict-free)
    const __half2* Wh2 = (const __half2*)Wh;
#pragma unroll
    for (int r = 0; r < 2; r++) {
        const int k = r * 512 + tid;
        const __half2* wk = Wh2 + (size_t)k * 32;
        float ta[4] = {0.f, 0.f, 0.f, 0.f};
#pragma unroll 8
        for (int qw = 0; qw < 32; qw++) {
            const int m = (lane + qw) & 31;
            const float2 wv = __half22float2(wk[m]);
#pragma unroll
            for (int bl = 0; bl < 4; bl++) {
                const float2 o = out2[bl * 32 + m];
                ta[bl] = fmaf(wv.x, o.x, fmaf(wv.y, o.y, ta[bl]));
            }
        }
#pragma unroll
        for (int bl = 0; bl < 4; bl++)
            g_t[((size_t)(b0 + bl) * NCAP + i) * DIN + k] = ta[bl];
    }
}

// ---------------- pass_route: logits (x.t) -> softmax over i -> y partials ----------------
#define JT 256
#define KP 64
#define NPAN (DIN / KP)       // 16
#define XPITH 72
#define XBUF_H (JT * XPITH)
#define TPIT 20
#define CPIT 20
#define X_BYTES (2 * XBUF_H * 2)
#define T_OFF   X_BYTES
#define C_OFF   (T_OFF + 1024 * TPIT * 4)
#define PASS_SMEM (C_OFF + JT * CPIT * 4)

__global__ __launch_bounds__(512) void pass_route() {
    extern __shared__ char smb[];
    __half* x_s = (__half*)smb;
    float*  t_t = (float*)(smb + T_OFF);
    float*  c_s = (float*)(smb + C_OFF);
    const uint32_t sb = smem_u32(smb);

    const int jc = blockIdx.x, b = blockIdx.y, tid = threadIdx.x;
    const int j0 = jc * JT;

    for (int e = tid; e < NCAP * DIN; e += 512) {
        const int i = e >> 10, k = e & 1023;
        t_t[k * TPIT + i] = g_t[((size_t)b * NCAP + i) * DIN + k];
    }

    auto load_panel = [&](int p) {
        const uint32_t base = sb + (uint32_t)(p & 1) * (XBUF_H * 2);
        const __half* src = g_xh + ((size_t)b * NIN + j0) * DIN + p * KP;
        for (int e = tid; e < JT * 8; e += 512) {
            const int j = e >> 3, c16 = e & 7;
            cp16(base + j * (XPITH * 2) + c16 * 16, src + (size_t)j * DIN + c16 * 8);
        }
        cp_commit();
    };
    load_panel(0);
    load_panel(1);
    __syncthreads();

    const int lane = tid & 31, w = tid >> 5;
    const int jq = lane >> 2, ig = lane & 3;
    float la[2][4];
#pragma unroll
    for (int r = 0; r < 2; r++)
#pragma unroll
        for (int q = 0; q < 4; q++) la[r][q] = 0.f;

    for (int p = 0; p < NPAN; p++) {
        if (p + 2 < NPAN) asm volatile("cp.async.wait_group 1;\n" ::: "memory");
        else              asm volatile("cp.async.wait_group 0;\n" ::: "memory");
        __syncthreads();
        const __half* xp0 = x_s + (p & 1) * XBUF_H + (w * 16 + jq) * XPITH;
        const __half* xp1 = xp0 + 8 * XPITH;
        const float*  tp  = t_t + (p * KP) * TPIT + ig * 4;
#pragma unroll 16
        for (int k = 0; k < KP; k++) {
            const float4 tv = *(const float4*)(tp + k * TPIT);
            const float x0 = __half2float(xp0[k]);
            const float x1 = __half2float(xp1[k]);
            la[0][0] = fmaf(x0, tv.x, la[0][0]);
            la[0][1] = fmaf(x0, tv.y, la[0][1]);
            la[0][2] = fmaf(x0, tv.z, la[0][2]);
            la[0][3] = fmaf(x0, tv.w, la[0][3]);
            la[1][0] = fmaf(x1, tv.x, la[1][0]);
            la[1][1] = fmaf(x1, tv.y, la[1][1]);
            la[1][2] = fmaf(x1, tv.z, la[1][2]);
            la[1][3] = fmaf(x1, tv.w, la[1][3]);
        }
        __syncthreads();
        if (p + 2 < NPAN) load_panel(p + 2);
    }

    load_panel(0);
    load_panel(1);

#pragma unroll
    for (int r = 0; r < 2; r++) {
        const int j = w * 16 + jq + r * 8;
        *(float4*)&c_s[j * CPIT + ig * 4] = make_float4(la[r][0], la[r][1], la[r][2], la[r][3]);
    }
    __syncthreads();

#pragma unroll
    for (int r = 0; r < 8; r++) {
        const int j = r * 32 + (tid >> 4), i = tid & 15;
        const float v = c_s[j * CPIT + i];
        float m = v;
#pragma unroll
        for (int o = 1; o < 16; o <<= 1) m = fmaxf(m, __shfl_xor_sync(0xffffffffu, m, o));
        const float e = expf(v - m);
        float s2 = e;
#pragma unroll
        for (int o = 1; o < 16; o <<= 1) s2 += __shfl_xor_sync(0xffffffffu, s2, o);
        c_s[j * CPIT + i] = e / s2;
    }
    __syncthreads();

    const int kk = tid & 31, ig2 = (tid >> 5) & 3, jq2 = tid >> 7;
    for (int p = 0; p < NPAN; p++) {
        if (p + 2 < NPAN) asm volatile("cp.async.wait_group 1;\n" ::: "memory");
        else              asm volatile("cp.async.wait_group 0;\n" ::: "memory");
        __syncthreads();
        const __half* xb = x_s + (p & 1) * XBUF_H + (jq2 * 64) * XPITH;
        const float*  cb = c_s + (jq2 * 64) * CPIT + ig2 * 4;
        float a0[4] = {0.f, 0.f, 0.f, 0.f};
        float a1[4] = {0.f, 0.f, 0.f, 0.f};
#pragma unroll 8
        for (int j = 0; j < 64; j++) {
            const float4 cv = *(const float4*)(cb + j * CPIT);
            const float xv0 = __half2float(xb[j * XPITH + kk]);
            const float xv1 = __half2float(xb[j * XPITH + kk + 32]);
            a0[0] = fmaf(cv.x, xv0, a0[0]);
            a0[1] = fmaf(cv.y, xv0, a0[1]);
            a0[2] = fmaf(cv.z, xv0, a0[2]);
            a0[3] = fmaf(cv.w, xv0, a0[3]);
            a1[0] = fmaf(cv.x, xv1, a1[0]);
            a1[1] = fmaf(cv.y, xv1, a1[1]);
            a1[2] = fmaf(cv.z, xv1, a1[2]);
            a1[3] = fmaf(cv.w, xv1, a1[3]);
        }
        const int kg = p * KP + kk;
#pragma unroll
        for (int q = 0; q < 4; q++) {
            g_ypart[jc * 4 + jq2][b][ig2 * 4 + q][kg]      = a0[q];
            g_ypart[jc * 4 + jq2][b][ig2 * 4 + q][kg + 32] = a1[q];
        }
        __syncthreads();
        if (p + 2 < NPAN) load_panel(p + 2);
    }
}

// ---------------- launch ----------------
extern "C" void kernel_launch(void* const* d_in, const int* in_sizes, int n_in,
                              void* d_out, int out_size) {
    const float* x = (const float*)d_in[0];
    const float* W = (const float*)d_in[1];
    if (in_sizes[0] == DIN * NCAP * DCAP && in_sizes[1] == (int)((size_t)BATCH * NIN * DIN)) {
        const float* t = x; x = W; W = t;
    }
    float* out = (float*)d_out;

    cudaFuncSetAttribute(kA2, cudaFuncAttributeMaxDynamicSharedMemorySize, KA_SMEM);
    cudaFuncSetAttribute(pass_route, cudaFuncAttributeMaxDynamicSharedMemorySize, PASS_SMEM);

    wh16_kernel<<<128, 256>>>(W);
    pass0<<<dim3(8, BATCH), 256>>>(x);
    kA2<<<dim3(NCAP, 16), 512, KA_SMEM>>>(out, 0);    // iter0: out0, t0
    pass_route<<<dim3(2, BATCH), 512, PASS_SMEM>>>(); // iter1: logits/softmax/y1
    kA2<<<dim3(NCAP, 16), 512, KA_SMEM>>>(out, 1);    // iter1: out1, t1
    pass_route<<<dim3(2, BATCH), 512, PASS_SMEM>>>(); // iter2: logits/softmax/y2
    kA2<<<dim3(NCAP, 16), 512, KA_SMEM>>>(out, 2);    // iter2: final out -> d_out
}

// round 10
// speedup vs baseline: 4.4758x; 1.9142x over previous
#include <cuda_runtime.h>
#include <cuda_fp16.h>
#include <cstdint>

#define BATCH 64
#define NCAP  16
#define DCAP  64
#define NIN   512
#define DIN   1024

// ---------------- scratch (allocation-free: __device__ globals) ----------------
__device__ __half g_xh[(size_t)BATCH * NIN * DIN];       // 64 MB, x f16 [b][j][k]
__device__ __half g_wh16[(size_t)DIN * NCAP * DCAP];     // 2 MB, W f16 [k][n]
__device__ float  g_xsump[8][BATCH][DIN];                // 2 MB, partial x sums over j
__device__ __half g_t16[(size_t)BATCH * NCAP * DIN];     // 2 MB, t f16 [b][i][k]
__device__ float  g_ypart[4][BATCH][NCAP][DIN];          // 16 MB, y partials

// ---------------- helpers ----------------
__device__ __forceinline__ uint32_t smem_u32(const void* p) {
    uint32_t a;
    asm("{ .reg .u64 t; cvta.to.shared.u64 t, %1; cvt.u32.u64 %0, t; }" : "=r"(a) : "l"(p));
    return a;
}
__device__ __forceinline__ void cp16(uint32_t dst, const void* src) {
    asm volatile("cp.async.cg.shared.global [%0], [%1], 16;\n" :: "r"(dst), "l"(src));
}
__device__ __forceinline__ void cp_commit() { asm volatile("cp.async.commit_group;\n" ::: "memory"); }

__device__ __forceinline__ void hmma(float* d, const uint32_t* a, const uint32_t* b) {
    asm volatile(
        "mma.sync.aligned.m16n8k16.row.col.f32.f16.f16.f32 "
        "{%0,%1,%2,%3}, {%4,%5,%6,%7}, {%8,%9}, {%0,%1,%2,%3};\n"
        : "+f"(d[0]), "+f"(d[1]), "+f"(d[2]), "+f"(d[3])
        : "r"(a[0]), "r"(a[1]), "r"(a[2]), "r"(a[3]), "r"(b[0]), "r"(b[1]));
}
__device__ __forceinline__ void ldsm_x4(uint32_t* r, uint32_t addr) {
    asm volatile("ldmatrix.sync.aligned.m8n8.x4.shared.b16 {%0,%1,%2,%3}, [%4];"
                 : "=r"(r[0]), "=r"(r[1]), "=r"(r[2]), "=r"(r[3]) : "r"(addr));
}
__device__ __forceinline__ void ldsm_x2t(uint32_t* r, uint32_t addr) {
    asm volatile("ldmatrix.sync.aligned.m8n8.x2.trans.shared.b16 {%0,%1}, [%2];"
                 : "=r"(r[0]), "=r"(r[1]) : "r"(addr));
}

// ---------------- prep: W f32 -> f16 ----------------
__global__ __launch_bounds__(256) void wh16_kernel(const float* __restrict__ W) {
    const size_t n4 = (size_t)DIN * 1024 / 4;
    for (size_t e = (size_t)blockIdx.x * blockDim.x + threadIdx.x; e < n4;
         e += (size_t)gridDim.x * blockDim.x) {
        float4 v = ((const float4*)W)[e];
        __half2* dst = (__half2*)g_wh16 + e * 2;
        dst[0] = __floats2half2_rn(v.x, v.y);
        dst[1] = __floats2half2_rn(v.z, v.w);
    }
}

// ---------------- pass0: xsum partials + x -> f16 ----------------
__global__ __launch_bounds__(256) void pass0(const float* __restrict__ X) {
    const int c = blockIdx.x, b = blockIdx.y, tid = threadIdx.x;
    const size_t rowbase = ((size_t)b * NIN + c * 64) * DIN;
    const float4* xp = (const float4*)(X + rowbase) + tid;
    uint2* xh = (uint2*)(g_xh + rowbase) + tid;
    float4 a = make_float4(0.f, 0.f, 0.f, 0.f);
#pragma unroll 4
    for (int j = 0; j < 64; j++) {
        const float4 v = xp[j * (DIN / 4)];
        a.x += v.x; a.y += v.y; a.z += v.z; a.w += v.w;
        const __half2 h0 = __floats2half2_rn(v.x, v.y);
        const __half2 h1 = __floats2half2_rn(v.z, v.w);
        uint2 u;
        u.x = *(const unsigned*)&h0;
        u.y = *(const unsigned*)&h1;
        xh[j * (DIN / 4)] = u;
    }
    ((float4*)g_xsump[c][b])[tid] = a;
}

// ---------------- kA2: y -> z = y@W_i -> out = squash(z) -> t16 = W_i@out ----------------
#define KA_Y_OFF (DIN * DCAP * 2)                    // 131072
#define KA_Z_OFF (KA_Y_OFF + 4 * DIN * 4)            // +16384
#define KA_O_OFF (KA_Z_OFF + 8 * 4 * 64 * 4)         // +8192
#define KA_SMEM  (KA_O_OFF + 4 * 32 * 8)             // 156672

__global__ __launch_bounds__(512) void kA2(float* __restrict__ d_out, int stage) {
    extern __shared__ char smb[];
    const uint32_t sb = smem_u32(smb);
    __half*  Wh   = (__half*)smb;                        // [1024][64]
    float*   y_s  = (float*)(smb + KA_Y_OFF);            // [4][1024]
    float*   zred = (float*)(smb + KA_Z_OFF);            // [8][4][64]
    float2*  out2 = (float2*)(smb + KA_O_OFF);           // [4][32]

    const int i = blockIdx.x, bg = blockIdx.y, tid = threadIdx.x;
    const int b0 = bg * 4;
    const int lane = tid & 31;

    {
        const __half* src = g_wh16 + i * 64;
#pragma unroll 4
        for (int e = tid; e < 8192; e += 512) {
            const int k = e >> 3, c = e & 7;
            cp16(sb + k * 128 + c * 16, src + (size_t)k * 1024 + c * 8);
        }
        cp_commit();
    }

    for (int e = tid; e < 4 * DIN; e += 512) {
        const int bl = e >> 10, k = e & 1023;
        float v = 0.f;
        if (stage == 0) {
#pragma unroll
            for (int p = 0; p < 8; p++) v += g_xsump[p][b0 + bl][k];
            v *= (1.f / 16.f);
        } else {
#pragma unroll
            for (int p = 0; p < 4; p++) v += g_ypart[p][b0 + bl][i][k];
        }
        y_s[e] = v;
    }
    asm volatile("cp.async.wait_group 0;\n" ::: "memory");
    __syncthreads();

    {
        const int ks = tid >> 6, d = tid & 63;
        float acc[4] = {0.f, 0.f, 0.f, 0.f};
        const __half* wp = Wh + (size_t)(ks * 128) * 64 + d;
#pragma unroll 8
        for (int k2 = 0; k2 < 128; k2++) {
            const float w = __half2float(wp[k2 * 64]);
            const int k = ks * 128 + k2;
#pragma unroll
            for (int bl = 0; bl < 4; bl++)
                acc[bl] = fmaf(y_s[bl * 1024 + k], w, acc[bl]);
        }
#pragma unroll
        for (int bl = 0; bl < 4; bl++) zred[(ks * 4 + bl) * 64 + d] = acc[bl];
    }
    __syncthreads();

    if (tid < 128) {
        const int bl = tid >> 5;
        float za = 0.f, zb = 0.f;
#pragma unroll
        for (int p = 0; p < 8; p++) {
            za += zred[(p * 4 + bl) * 64 + 2 * lane];
            zb += zred[(p * 4 + bl) * 64 + 2 * lane + 1];
        }
        float sq = za * za + zb * zb;
#pragma unroll
        for (int o = 16; o; o >>= 1) sq += __shfl_xor_sync(0xffffffffu, sq, o);
        const float inv = 1.0f / sqrtf(sq + 1e-7f);
        const float ox = za * inv, oy = zb * inv;
        out2[bl * 32 + lane] = make_float2(ox, oy);
        if (stage == 2) {
            float2* dp = (float2*)(d_out + ((size_t)(b0 + bl) * NCAP + i) * DCAP);
            dp[lane] = make_float2(ox, oy);
        }
    }
    __syncthreads();
    if (stage == 2) return;

    const __half2* Wh2 = (const __half2*)Wh;
#pragma unroll
    for (int r = 0; r < 2; r++) {
        const int k = r * 512 + tid;
        const __half2* wk = Wh2 + (size_t)k * 32;
        float ta[4] = {0.f, 0.f, 0.f, 0.f};
#pragma unroll 8
        for (int qw = 0; qw < 32; qw++) {
            const int m = (lane + qw) & 31;
            const float2 wv = __half22float2(wk[m]);
#pragma unroll
            for (int bl = 0; bl < 4; bl++) {
                const float2 o = out2[bl * 32 + m];
                ta[bl] = fmaf(wv.x, o.x, fmaf(wv.y, o.y, ta[bl]));
            }
        }
#pragma unroll
        for (int bl = 0; bl < 4; bl++)
            g_t16[((size_t)(b0 + bl) * NCAP + i) * DIN + k] = __float2half_rn(ta[bl]);
    }
}

// ---------------- pass_route2: tensor-core logits + softmax + tensor-core y ----------------
// grid (4 jchunk of 128, 64 b), 256 threads (8 warps), ~84.5 KB SMEM, 2 CTAs/SM.
#define JT2   128
#define XPB   144                 // x panel row pitch bytes (72 halves)
#define XBUF  (JT2 * XPB)         // 18432
#define T_OFF2 (2 * XBUF)         // 36864
#define TPB   2064                // t16 row pitch bytes (1032 halves)
#define CF_OFF (T_OFF2 + 16 * TPB)       // 69888
#define CFP   20                  // logits f32 pitch (floats)
#define C16_OFF (CF_OFF + JT2 * CFP * 4) // 80128
#define C16P  136                 // c16 row pitch halves
#define PASS2_SMEM (C16_OFF + 16 * C16P * 2)  // 84480

__global__ __launch_bounds__(256, 2) void pass_route2() {
    extern __shared__ char smb[];
    const uint32_t sb = smem_u32(smb);
    const int jc = blockIdx.x, b = blockIdx.y, tid = threadIdx.x;
    const int lane = tid & 31, w = tid >> 5;
    const int j0 = jc * JT2;

    // stage t16[b]: 16 rows x 1024 halves
    {
        const __half* src = g_t16 + (size_t)b * NCAP * DIN;
        for (int e = tid; e < 2048; e += 256) {
            const int r = e >> 7, c = e & 127;
            cp16(sb + T_OFF2 + r * TPB + c * 16, src + (size_t)r * DIN + c * 8);
        }
        cp_commit();
    }
    auto load_panel = [&](int p) {
        const uint32_t base = sb + (uint32_t)(p & 1) * XBUF;
        const __half* src = g_xh + ((size_t)(b * NIN + j0)) * DIN + p * 64;
        for (int e = tid; e < 1024; e += 256) {
            const int j = e >> 3, c = e & 7;
            cp16(base + j * XPB + c * 16, src + (size_t)j * DIN + c * 8);
        }
        cp_commit();
    };
    load_panel(0);
    load_panel(1);

    // ---- phase 1: logits = X(128x1024) @ t16^T(16x1024) via mma ----
    const uint32_t a_base  = sb + (w * 16 + (lane & 15)) * XPB + ((lane >> 4) & 1) * 16;
    const uint32_t bT_base = sb + T_OFF2 + (lane & 15) * TPB + ((lane >> 4) & 1) * 16;

    float la[2][4];
#pragma unroll
    for (int f = 0; f < 2; f++)
#pragma unroll
        for (int q = 0; q < 4; q++) la[f][q] = 0.f;

    for (int p = 0; p < 16; p++) {
        if (p + 1 < 16) asm volatile("cp.async.wait_group 1;\n" ::: "memory");
        else            asm volatile("cp.async.wait_group 0;\n" ::: "memory");
        __syncthreads();
        const uint32_t xb = (uint32_t)(p & 1) * XBUF;
#pragma unroll
        for (int s = 0; s < 4; s++) {
            uint32_t af[4], bf[4];
            ldsm_x4(af, a_base + xb + s * 32);
            ldsm_x4(bf, bT_base + (p * 4 + s) * 32);
            const uint32_t b0r[2] = {bf[0], bf[2]};
            const uint32_t b1r[2] = {bf[1], bf[3]};
            hmma(la[0], af, b0r);
            hmma(la[1], af, b1r);
        }
        __syncthreads();
        if (p + 2 < 16) load_panel(p + 2);
    }

    // store logits to SMEM [j][i] (pitch 20 f32)
    {
        float* cf = (float*)(smb + CF_OFF);
        const int jr = w * 16 + (lane >> 2);
        const int ic = (lane & 3) * 2;
#pragma unroll
        for (int f = 0; f < 2; f++) {
            *(float2*)&cf[jr * CFP + f * 8 + ic]       = make_float2(la[f][0], la[f][1]);
            *(float2*)&cf[(jr + 8) * CFP + f * 8 + ic] = make_float2(la[f][2], la[f][3]);
        }
    }
    // restart x panels for phase 3 (buffers free after final phase-1 sync)
    load_panel(0);
    load_panel(1);
    __syncthreads();

    // ---- phase 2: softmax over the 16 capsules per j; write c16 [i][j] f16 ----
    {
        const float* cf  = (const float*)(smb + CF_OFF);
        __half* c16 = (__half*)(smb + C16_OFF);
#pragma unroll
        for (int it = 0; it < 8; it++) {
            const int j = it * 16 + (tid >> 4), i = tid & 15;
            const float v = cf[j * CFP + i];
            float m = v;
#pragma unroll
            for (int o = 1; o < 16; o <<= 1) m = fmaxf(m, __shfl_xor_sync(0xffffffffu, m, o));
            const float e = expf(v - m);
            float s = e;
#pragma unroll
            for (int o = 1; o < 16; o <<= 1) s += __shfl_xor_sync(0xffffffffu, s, o);
            c16[i * C16P + j] = __float2half_rn(e / s);
        }
    }
    __syncthreads();

    // ---- phase 3: y(16x1024) = c16(16x128) @ X(128x1024), A frags cached in regs ----
    uint32_t aj[8][4];
    {
        const uint32_t ca = sb + C16_OFF + (lane & 15) * (C16P * 2) + ((lane >> 4) & 1) * 16;
#pragma unroll
        for (int js = 0; js < 8; js++) ldsm_x4(aj[js], ca + js * 32);
    }

    const uint32_t bx_base = sb + (lane & 15) * XPB + w * 16;
    for (int p = 0; p < 16; p++) {
        if (p + 1 < 16) asm volatile("cp.async.wait_group 1;\n" ::: "memory");
        else            asm volatile("cp.async.wait_group 0;\n" ::: "memory");
        __syncthreads();
        const uint32_t xb = (uint32_t)(p & 1) * XBUF;
        float ya[4] = {0.f, 0.f, 0.f, 0.f};
#pragma unroll
        for (int js = 0; js < 8; js++) {
            uint32_t bf[2];
            ldsm_x2t(bf, bx_base + xb + js * 16 * XPB);
            hmma(ya, aj[js], bf);
        }
        const int i0 = lane >> 2;
        const int kc = p * 64 + w * 8 + (lane & 3) * 2;
        *(float2*)&g_ypart[jc][b][i0][kc]     = make_float2(ya[0], ya[1]);
        *(float2*)&g_ypart[jc][b][i0 + 8][kc] = make_float2(ya[2], ya[3]);
        __syncthreads();
        if (p + 2 < 16) load_panel(p + 2);
    }
}

// ---------------- launch ----------------
extern "C" void kernel_launch(void* const* d_in, const int* in_sizes, int n_in,
                              void* d_out, int out_size) {
    const float* x = (const float*)d_in[0];
    const float* W = (const float*)d_in[1];
    if (in_sizes[0] == DIN * NCAP * DCAP && in_sizes[1] == (int)((size_t)BATCH * NIN * DIN)) {
        const float* t = x; x = W; W = t;
    }
    float* out = (float*)d_out;

    cudaFuncSetAttribute(kA2, cudaFuncAttributeMaxDynamicSharedMemorySize, KA_SMEM);
    cudaFuncSetAttribute(pass_route2, cudaFuncAttributeMaxDynamicSharedMemorySize, PASS2_SMEM);

    wh16_kernel<<<128, 256>>>(W);
    pass0<<<dim3(8, BATCH), 256>>>(x);
    kA2<<<dim3(NCAP, 16), 512, KA_SMEM>>>(out, 0);        // iter0: out0, t0
    pass_route2<<<dim3(4, BATCH), 256, PASS2_SMEM>>>();   // iter1: logits/softmax/y1
    kA2<<<dim3(NCAP, 16), 512, KA_SMEM>>>(out, 1);        // iter1: out1, t1
    pass_route2<<<dim3(4, BATCH), 256, PASS2_SMEM>>>();   // iter2: logits/softmax/y2
    kA2<<<dim3(NCAP, 16), 512, KA_SMEM>>>(out, 2);        // iter2: final out
}

// round 11
// speedup vs baseline: 4.6617x; 1.0415x over previous
#include <cuda_runtime.h>
#include <cuda_fp16.h>
#include <cstdint>

#define BATCH 64
#define NCAP  16
#define DCAP  64
#define NIN   512
#define DIN   1024

// ---------------- scratch (allocation-free: __device__ globals) ----------------
__device__ __half g_xh[(size_t)BATCH * NIN * DIN];       // 64 MB, x f16 [b][j][k]
__device__ __half g_wh16[(size_t)DIN * NCAP * DCAP];     // 2 MB, W f16 [k][n]
__device__ float  g_xsump[8][BATCH][DIN];                // 2 MB, partial x sums over j
__device__ __half g_t16[(size_t)BATCH * NCAP * DIN];     // 2 MB, t f16 [b][i][k]
__device__ float  g_ypart[4][BATCH][NCAP][DIN];          // 16 MB, y partials

// ---------------- helpers ----------------
__device__ __forceinline__ uint32_t smem_u32(const void* p) {
    uint32_t a;
    asm("{ .reg .u64 t; cvta.to.shared.u64 t, %1; cvt.u32.u64 %0, t; }" : "=r"(a) : "l"(p));
    return a;
}
__device__ __forceinline__ void cp16(uint32_t dst, const void* src) {
    asm volatile("cp.async.cg.shared.global [%0], [%1], 16;\n" :: "r"(dst), "l"(src));
}
__device__ __forceinline__ void cp_commit() { asm volatile("cp.async.commit_group;\n" ::: "memory"); }

__device__ __forceinline__ void hmma(float* d, const uint32_t* a, const uint32_t* b) {
    asm volatile(
        "mma.sync.aligned.m16n8k16.row.col.f32.f16.f16.f32 "
        "{%0,%1,%2,%3}, {%4,%5,%6,%7}, {%8,%9}, {%0,%1,%2,%3};\n"
        : "+f"(d[0]), "+f"(d[1]), "+f"(d[2]), "+f"(d[3])
        : "r"(a[0]), "r"(a[1]), "r"(a[2]), "r"(a[3]), "r"(b[0]), "r"(b[1]));
}
__device__ __forceinline__ void ldsm_x4(uint32_t* r, uint32_t addr) {
    asm volatile("ldmatrix.sync.aligned.m8n8.x4.shared.b16 {%0,%1,%2,%3}, [%4];"
                 : "=r"(r[0]), "=r"(r[1]), "=r"(r[2]), "=r"(r[3]) : "r"(addr));
}
__device__ __forceinline__ void ldsm_x2t(uint32_t* r, uint32_t addr) {
    asm volatile("ldmatrix.sync.aligned.m8n8.x2.trans.shared.b16 {%0,%1}, [%2];"
                 : "=r"(r[0]), "=r"(r[1]) : "r"(addr));
}

// ---------------- prep: W f32 -> f16 ----------------
__global__ __launch_bounds__(256) void wh16_kernel(const float* __restrict__ W) {
    const size_t n4 = (size_t)DIN * 1024 / 4;
    for (size_t e = (size_t)blockIdx.x * blockDim.x + threadIdx.x; e < n4;
         e += (size_t)gridDim.x * blockDim.x) {
        float4 v = ((const float4*)W)[e];
        __half2* dst = (__half2*)g_wh16 + e * 2;
        dst[0] = __floats2half2_rn(v.x, v.y);
        dst[1] = __floats2half2_rn(v.z, v.w);
    }
}

// ---------------- pass0: xsum partials + x -> f16 ----------------
__global__ __launch_bounds__(256) void pass0(const float* __restrict__ X) {
    const int c = blockIdx.x, b = blockIdx.y, tid = threadIdx.x;
    const size_t rowbase = ((size_t)b * NIN + c * 64) * DIN;
    const float4* xp = (const float4*)(X + rowbase) + tid;
    uint2* xh = (uint2*)(g_xh + rowbase) + tid;
    float4 a = make_float4(0.f, 0.f, 0.f, 0.f);
#pragma unroll 4
    for (int j = 0; j < 64; j++) {
        const float4 v = xp[j * (DIN / 4)];
        a.x += v.x; a.y += v.y; a.z += v.z; a.w += v.w;
        const __half2 h0 = __floats2half2_rn(v.x, v.y);
        const __half2 h1 = __floats2half2_rn(v.z, v.w);
        uint2 u;
        u.x = *(const unsigned*)&h0;
        u.y = *(const unsigned*)&h1;
        xh[j * (DIN / 4)] = u;
    }
    ((float4*)g_xsump[c][b])[tid] = a;
}

// ---------------- kA2: y -> z = y@W_i -> out = squash(z) -> t16 = W_i@out ----------------
// grid (16 i, 8 bgroup of 8) = 128 CTAs = one full wave. W_i slice f16 in SMEM, reused z+t.
#define KAB 8
#define KA_Y_OFF (DIN * DCAP * 2)                    // 131072
#define KA_Z_OFF (KA_Y_OFF + KAB * DIN * 4)          // +32768
#define KA_O_OFF (KA_Z_OFF + 8 * KAB * 64 * 4)       // +16384
#define KA_SMEM  (KA_O_OFF + KAB * 32 * 8)           // +2048 = 182272

__global__ __launch_bounds__(512) void kA2(float* __restrict__ d_out, int stage) {
    extern __shared__ char smb[];
    const uint32_t sb = smem_u32(smb);
    __half*  Wh   = (__half*)smb;                        // [1024][64]
    float*   y_s  = (float*)(smb + KA_Y_OFF);            // [8][1024]
    float*   zred = (float*)(smb + KA_Z_OFF);            // [8 ks][8 bl][64]
    float2*  out2 = (float2*)(smb + KA_O_OFF);           // [8][32]

    const int i = blockIdx.x, bg = blockIdx.y, tid = threadIdx.x;
    const int b0 = bg * KAB;
    const int lane = tid & 31;

    {
        const __half* src = g_wh16 + i * 64;
#pragma unroll 4
        for (int e = tid; e < 8192; e += 512) {
            const int k = e >> 3, c = e & 7;
            cp16(sb + k * 128 + c * 16, src + (size_t)k * 1024 + c * 8);
        }
        cp_commit();
    }

    for (int e = tid; e < KAB * DIN; e += 512) {
        const int bl = e >> 10, k = e & 1023;
        float v = 0.f;
        if (stage == 0) {
#pragma unroll
            for (int p = 0; p < 8; p++) v += g_xsump[p][b0 + bl][k];
            v *= (1.f / 16.f);
        } else {
#pragma unroll
            for (int p = 0; p < 4; p++) v += g_ypart[p][b0 + bl][i][k];
        }
        y_s[e] = v;
    }
    asm volatile("cp.async.wait_group 0;\n" ::: "memory");
    __syncthreads();

    // z: thread (ks = tid>>6 of 8 k-slices, d = tid&63), 8 batches
    {
        const int ks = tid >> 6, d = tid & 63;
        float acc[KAB];
#pragma unroll
        for (int q = 0; q < KAB; q++) acc[q] = 0.f;
        const __half* wp = Wh + (size_t)(ks * 128) * 64 + d;
#pragma unroll 4
        for (int k2 = 0; k2 < 128; k2++) {
            const float w = __half2float(wp[k2 * 64]);
            const int k = ks * 128 + k2;
#pragma unroll
            for (int bl = 0; bl < KAB; bl++)
                acc[bl] = fmaf(y_s[bl * 1024 + k], w, acc[bl]);
        }
#pragma unroll
        for (int bl = 0; bl < KAB; bl++) zred[(ks * KAB + bl) * 64 + d] = acc[bl];
    }
    __syncthreads();

    // reduce 8 slices + squash (8 warps, one batch each)
    if (tid < KAB * 32) {
        const int bl = tid >> 5;
        float za = 0.f, zb = 0.f;
#pragma unroll
        for (int p = 0; p < 8; p++) {
            za += zred[(p * KAB + bl) * 64 + 2 * lane];
            zb += zred[(p * KAB + bl) * 64 + 2 * lane + 1];
        }
        float sq = za * za + zb * zb;
#pragma unroll
        for (int o = 16; o; o >>= 1) sq += __shfl_xor_sync(0xffffffffu, sq, o);
        const float inv = 1.0f / sqrtf(sq + 1e-7f);
        const float ox = za * inv, oy = zb * inv;
        out2[bl * 32 + lane] = make_float2(ox, oy);
        if (stage == 2) {
            float2* dp = (float2*)(d_out + ((size_t)(b0 + bl) * NCAP + i) * DCAP);
            dp[lane] = make_float2(ox, oy);
        }
    }
    __syncthreads();
    if (stage == 2) return;

    // t16: thread covers k = tid and k + 512; rotated conflict-free W reads
    const __half2* Wh2 = (const __half2*)Wh;
#pragma unroll
    for (int r = 0; r < 2; r++) {
        const int k = r * 512 + tid;
        const __half2* wk = Wh2 + (size_t)k * 32;
        float ta[KAB];
#pragma unroll
        for (int q = 0; q < KAB; q++) ta[q] = 0.f;
#pragma unroll 4
        for (int qw = 0; qw < 32; qw++) {
            const int m = (lane + qw) & 31;
            const float2 wv = __half22float2(wk[m]);
#pragma unroll
            for (int bl = 0; bl < KAB; bl++) {
                const float2 o = out2[bl * 32 + m];
                ta[bl] = fmaf(wv.x, o.x, fmaf(wv.y, o.y, ta[bl]));
            }
        }
#pragma unroll
        for (int bl = 0; bl < KAB; bl++)
            g_t16[((size_t)(b0 + bl) * NCAP + i) * DIN + k] = __float2half_rn(ta[bl]);
    }
}

// ---------------- pass_route3: 3-buffer ring, one sync per panel ----------------
// grid (4 jchunk of 128, 64 b), 256 threads, ~100.5 KB SMEM, 2 CTAs/SM.
#define JT2   128
#define XPB   144
#define XBUF  (JT2 * XPB)                 // 18432
#define NBUF  3
#define T_OFF2 (NBUF * XBUF)              // 55296
#define TPB   2064
#define CF_OFF (T_OFF2 + 16 * TPB)        // 88320
#define CFP   20
#define C16_OFF (CF_OFF + JT2 * CFP * 4)  // 98560
#define C16P  136
#define PASS2_SMEM (C16_OFF + 16 * C16P * 2)  // 102912

__global__ __launch_bounds__(256, 2) void pass_route3() {
    extern __shared__ char smb[];
    const uint32_t sb = smem_u32(smb);
    const int jc = blockIdx.x, b = blockIdx.y, tid = threadIdx.x;
    const int lane = tid & 31, w = tid >> 5;
    const int j0 = jc * JT2;

    // stage t16[b] (group 0)
    {
        const __half* src = g_t16 + (size_t)b * NCAP * DIN;
        for (int e = tid; e < 2048; e += 256) {
            const int r = e >> 7, c = e & 127;
            cp16(sb + T_OFF2 + r * TPB + c * 16, src + (size_t)r * DIN + c * 8);
        }
        cp_commit();
    }
    auto load_panel = [&](int p) {
        const uint32_t base = sb + (uint32_t)(p % NBUF) * XBUF;
        const __half* src = g_xh + ((size_t)(b * NIN + j0)) * DIN + p * 64;
        for (int e = tid; e < 1024; e += 256) {
            const int j = e >> 3, c = e & 7;
            cp16(base + j * XPB + c * 16, src + (size_t)j * DIN + c * 8);
        }
        cp_commit();
    };
    load_panel(0);
    load_panel(1);

    // ---- phase 1: logits = X(128x1024) @ t16^T(16x1024) ----
    const uint32_t a_base  = sb + (w * 16 + (lane & 15)) * XPB + ((lane >> 4) & 1) * 16;
    const uint32_t bT_base = sb + T_OFF2 + (lane & 15) * TPB + ((lane >> 4) & 1) * 16;

    float la[2][4];
#pragma unroll
    for (int f = 0; f < 2; f++)
#pragma unroll
        for (int q = 0; q < 4; q++) la[f][q] = 0.f;

    for (int p = 0; p < 16; p++) {
        if (p < 14) asm volatile("cp.async.wait_group 1;\n" ::: "memory");
        else        asm volatile("cp.async.wait_group 0;\n" ::: "memory");
        __syncthreads();
        if (p + 2 < 16) load_panel(p + 2);   // overwrites buf consumed at p-1; safe after sync
        const uint32_t xb = (uint32_t)(p % NBUF) * XBUF;
#pragma unroll
        for (int s = 0; s < 4; s++) {
            uint32_t af[4], bf[4];
            ldsm_x4(af, a_base + xb + s * 32);
            ldsm_x4(bf, bT_base + (p * 4 + s) * 32);
            const uint32_t b0r[2] = {bf[0], bf[2]};
            const uint32_t b1r[2] = {bf[1], bf[3]};
            hmma(la[0], af, b0r);
            hmma(la[1], af, b1r);
        }
    }

    // store logits to SMEM [j][i]
    {
        float* cf = (float*)(smb + CF_OFF);
        const int jr = w * 16 + (lane >> 2);
        const int ic = (lane & 3) * 2;
#pragma unroll
        for (int f = 0; f < 2; f++) {
            *(float2*)&cf[jr * CFP + f * 8 + ic]       = make_float2(la[f][0], la[f][1]);
            *(float2*)&cf[(jr + 8) * CFP + f * 8 + ic] = make_float2(la[f][2], la[f][3]);
        }
    }
    __syncthreads();           // logits visible; all phase-1 consumption done
    load_panel(0);             // restart x stream for phase 3 (overlaps softmax)
    load_panel(1);

    // ---- phase 2: softmax over the 16 capsules per j -> c16 [i][j] f16 ----
    {
        const float* cf  = (const float*)(smb + CF_OFF);
        __half* c16 = (__half*)(smb + C16_OFF);
#pragma unroll
        for (int it = 0; it < 8; it++) {
            const int j = it * 16 + (tid >> 4), i = tid & 15;
            const float v = cf[j * CFP + i];
            float m = v;
#pragma unroll
            for (int o = 1; o < 16; o <<= 1) m = fmaxf(m, __shfl_xor_sync(0xffffffffu, m, o));
            const float e = expf(v - m);
            float s = e;
#pragma unroll
            for (int o = 1; o < 16; o <<= 1) s += __shfl_xor_sync(0xffffffffu, s, o);
            c16[i * C16P + j] = __float2half_rn(e / s);
        }
    }
    __syncthreads();

    // ---- phase 3: y(16x1024) = c16(16x128) @ X(128x1024) ----
    uint32_t aj[8][4];
    {
        const uint32_t ca = sb + C16_OFF + (lane & 15) * (C16P * 2) + ((lane >> 4) & 1) * 16;
#pragma unroll
        for (int js = 0; js < 8; js++) ldsm_x4(aj[js], ca + js * 32);
    }

    const uint32_t bx_base = sb + (lane & 15) * XPB + w * 16;
    for (int p = 0; p < 16; p++) {
        if (p < 14) asm volatile("cp.async.wait_group 1;\n" ::: "memory");
        else        asm volatile("cp.async.wait_group 0;\n" ::: "memory");
        __syncthreads();
        if (p + 2 < 16) load_panel(p + 2);
        const uint32_t xb = (uint32_t)(p % NBUF) * XBUF;
        float ya[4] = {0.f, 0.f, 0.f, 0.f};
#pragma unroll
        for (int js = 0; js < 8; js++) {
            uint32_t bf[2];
            ldsm_x2t(bf, bx_base + xb + js * 16 * XPB);
            hmma(ya, aj[js], bf);
        }
        const int i0 = lane >> 2;
        const int kc = p * 64 + w * 8 + (lane & 3) * 2;
        *(float2*)&g_ypart[jc][b][i0][kc]     = make_float2(ya[0], ya[1]);
        *(float2*)&g_ypart[jc][b][i0 + 8][kc] = make_float2(ya[2], ya[3]);
    }
}

// ---------------- launch ----------------
extern "C" void kernel_launch(void* const* d_in, const int* in_sizes, int n_in,
                              void* d_out, int out_size) {
    const float* x = (const float*)d_in[0];
    const float* W = (const float*)d_in[1];
    if (in_sizes[0] == DIN * NCAP * DCAP && in_sizes[1] == (int)((size_t)BATCH * NIN * DIN)) {
        const float* t = x; x = W; W = t;
    }
    float* out = (float*)d_out;

    cudaFuncSetAttribute(kA2, cudaFuncAttributeMaxDynamicSharedMemorySize, KA_SMEM);
    cudaFuncSetAttribute(pass_route3, cudaFuncAttributeMaxDynamicSharedMemorySize, PASS2_SMEM);

    wh16_kernel<<<128, 256>>>(W);
    pass0<<<dim3(8, BATCH), 256>>>(x);
    kA2<<<dim3(NCAP, 8), 512, KA_SMEM>>>(out, 0);         // iter0: out0, t0
    pass_route3<<<dim3(4, BATCH), 256, PASS2_SMEM>>>();   // iter1: logits/softmax/y1
    kA2<<<dim3(NCAP, 8), 512, KA_SMEM>>>(out, 1);         // iter1: out1, t1
    pass_route3<<<dim3(4, BATCH), 256, PASS2_SMEM>>>();   // iter2: logits/softmax/y2
    kA2<<<dim3(NCAP, 8), 512, KA_SMEM>>>(out, 2);         // iter2: final out
}